// round 16
// baseline (speedup 1.0000x reference)
#include <cuda_runtime.h>
#include <cuda_fp16.h>
#include <math.h>
#include <mma.h>
#include <stdint.h>

using namespace nvcuda;

#define NS   1024
#define NM   128
#define ND   1024
#define NH   16
#define NHD  64
#define NF   2048
#define NL   8
#define NCAT 1280   /* S + 2M */
#define NKV  1152   /* M + S  */
#define NPOS 1280

/* ------------------------------------------------------------------ */
__device__ float g_cat[NCAT*ND];
__device__ __align__(256) __half g_xh [NCAT*ND];
__device__ float g_q  [NS*ND];
__device__ float g_k  [NKV*ND];
__device__ float g_v  [NKV*ND];
__device__ float g_qbf[2*NM*ND];
__device__ float g_kbf[2*NM*ND];
__device__ float g_vbf[2*NM*ND];
__device__ __align__(256) __half g_atth[NCAT*ND];
__device__ float g_m1 [NCAT*NF];
__device__ float g_m2 [NCAT*NF];
__device__ __align__(256) __half g_m1h[NCAT*NF];
__device__ float g_inj[NL*NM*ND];
__device__ float g_fg [NL*NM*ND];
__device__ __align__(256) __half g_memh[7*NM*ND];
__device__ float g_cs [NPOS*32];
__device__ float g_sn [NPOS*32];

/* pre-rounded fp16 weights, 7 layers each */
#define WDD (7*ND*ND)
#define WDF (7*ND*NF)
__device__ __align__(256) __half g_wq [WDD]; __device__ __align__(256) __half g_wk [WDD];
__device__ __align__(256) __half g_wv [WDD]; __device__ __align__(256) __half g_wo [WDD];
__device__ __align__(256) __half g_mwk[WDD]; __device__ __align__(256) __half g_mwv[WDD];
__device__ __align__(256) __half g_bwq[WDD]; __device__ __align__(256) __half g_bwk[WDD];
__device__ __align__(256) __half g_bwv[WDD]; __device__ __align__(256) __half g_fwq[WDD];
__device__ __align__(256) __half g_fwk[WDD]; __device__ __align__(256) __half g_fwv[WDD];
__device__ __align__(256) __half g_wg [WDF]; __device__ __align__(256) __half g_wu [WDF];
__device__ __align__(256) __half g_wd [WDF];

/* ------------------------------------------------------------------ */
__global__ void init_tables_kernel() {
    int idx = blockIdx.x*blockDim.x + threadIdx.x;
    if (idx >= NPOS*32) return;
    int pos = idx >> 5, j = idx & 31;
    double inv = exp(-((double)(2*j)/64.0) * log(10000.0));
    double a = (double)pos * inv;
    g_cs[idx] = (float)cos(a);
    g_sn[idx] = (float)sin(a);
}

__global__ void gather_kernel(const int* __restrict__ ids,
                              const float* __restrict__ embed,
                              float* __restrict__ out) {
    int row = blockIdx.x;
    int id  = ids[row];
    const float4* src = (const float4*)(embed + (size_t)id*ND);
    float4* dst = (float4*)(out + (size_t)row*ND);
    dst[threadIdx.x] = src[threadIdx.x];
}

/* batched fp32 -> fp16 rounding (one layer's weights per call)       */
struct RoundJob  { const float* s; __half* d; int n4; };
struct RoundJobs { RoundJob j[16]; };

__global__ void round_w_kernel(RoundJobs js) {
    RoundJob jb = js.j[blockIdx.y];
    const float4* s = (const float4*)jb.s;
    __half2* d = (__half2*)jb.d;
    int stride = gridDim.x*blockDim.x;
    for (int i = blockIdx.x*blockDim.x + threadIdx.x; i < jb.n4; i += stride) {
        float4 v = s[i];
        d[2*i]   = __floats2half2_rn(v.x, v.y);
        d[2*i+1] = __floats2half2_rn(v.z, v.w);
    }
}

/* RMSNorm -> fp16; one float4/thread, warp-shfl reduce, 1 barrier.   */
/* If rec_inj set: row<NM records raw row to rec_inj, else rec_fg.    */
__global__ void rmsnorm_kernel(const float* __restrict__ x,
                               const float* __restrict__ w,
                               __half* __restrict__ y,
                               float* __restrict__ rec_inj,
                               float* __restrict__ rec_fg) {
    int row = blockIdx.x, t = threadIdx.x;
    const float4* xr = (const float4*)(x + (size_t)row*ND);
    float4 v4 = xr[t];
    float s = v4.x*v4.x + v4.y*v4.y + v4.z*v4.z + v4.w*v4.w;
    #pragma unroll
    for (int o = 16; o; o >>= 1) s += __shfl_xor_sync(0xffffffffu, s, o);
    __shared__ float red[8];
    if ((t & 31) == 0) red[t>>5] = s;
    __syncthreads();
    float tot = red[0]+red[1]+red[2]+red[3]+red[4]+red[5]+red[6]+red[7];
    float r = rsqrtf(tot*(1.f/ND) + 1e-5f);
    if (rec_inj) {
        float* dst = (row < NM) ? rec_inj + (size_t)row*ND
                                : rec_fg  + (size_t)(row-NM)*ND;
        ((float4*)dst)[t] = v4;
    }
    float4 wv = ((const float4*)w)[t];
    __half2* yr = (__half2*)(y + (size_t)row*ND);
    yr[2*t]   = __floats2half2_rn(v4.x*wv.x*r, v4.y*wv.y*r);
    yr[2*t+1] = __floats2half2_rn(v4.z*wv.z*r, v4.w*wv.w*r);
}

/* ------------------------------------------------------------------ */
/* fp16 WMMA GEMM: 128x128 CTA tile, 4 warps (64x64), BK=32, 3-stage  */
/* ------------------------------------------------------------------ */
struct GemmDesc  { const __half* A; const __half* B; float* C; };
struct GemmBatch { GemmDesc d[12]; unsigned char yd[40]; unsigned char yr[40]; };

typedef wmma::fragment<wmma::matrix_a, 16,16,16, __half, wmma::row_major> HFragA;
typedef wmma::fragment<wmma::matrix_b, 16,16,16, __half, wmma::row_major> HFragB;
typedef wmma::fragment<wmma::accumulator, 16,16,16, float> HFragC;

#define GSTAGES 3
#define HA_STRIDE 40
#define HB_STRIDE 136
#define HA_TILE (128*HA_STRIDE)
#define HB_TILE (32*HB_STRIDE)
#define GSMEM_BYTES (GSTAGES*(HA_TILE + HB_TILE)*2)

__device__ __forceinline__ void cp16(uint32_t dst, const void* src) {
    asm volatile("cp.async.cg.shared.global [%0], [%1], 16;" :: "r"(dst), "l"(src));
}
__device__ __forceinline__ void cp_commit() {
    asm volatile("cp.async.commit_group;");
}
__device__ __forceinline__ void cp_wait1() {
    asm volatile("cp.async.wait_group 1;");
}

__device__ __forceinline__ void gemm_core(const __half* __restrict__ A,
                                          const __half* __restrict__ B,
                                          float* __restrict__ C,
                                          int N, int K, int beta, int rowblk) {
    extern __shared__ __half smh[];
    __half* Asm = smh;
    __half* Bsm = smh + GSTAGES*HA_TILE;

    int tid = threadIdx.x;
    int wid = tid >> 5;
    int wy  = wid >> 1;
    int wx  = wid & 1;
    size_t brow = (size_t)rowblk * 128;
    size_t bcol = (size_t)blockIdx.x * 128;

    int ar = tid >> 2, ac = (tid & 3) << 3;
    int br = tid >> 4, bc = (tid & 15) << 3;

    const __half* Ag = A + (brow + ar)*K + ac;
    const __half* Bg = B + (size_t)br*N + bcol + bc;

    uint32_t sA = (uint32_t)__cvta_generic_to_shared(Asm + ar*HA_STRIDE + ac);
    uint32_t sB = (uint32_t)__cvta_generic_to_shared(Bsm + br*HB_STRIDE + bc);
    const uint32_t aStageB = HA_TILE*2;
    const uint32_t bStageB = HB_TILE*2;

    int nt = K >> 5;

    #pragma unroll
    for (int s = 0; s < 2; s++) {
        int k0 = s << 5;
        #pragma unroll
        for (int i = 0; i < 4; i++)
            cp16(sA + s*aStageB + i*32*HA_STRIDE*2, Ag + k0 + (size_t)(32*i)*K);
        #pragma unroll
        for (int i = 0; i < 4; i++)
            cp16(sB + s*bStageB + i*8*HB_STRIDE*2, Bg + (size_t)(k0 + 8*i)*N);
        cp_commit();
    }

    HFragC acc[4][4];
    #pragma unroll
    for (int mi = 0; mi < 4; mi++)
        #pragma unroll
        for (int ni = 0; ni < 4; ni++)
            wmma::fill_fragment(acc[mi][ni], 0.f);

    int st = 0, ld = 2;
    for (int kt = 0; kt < nt; kt++) {
        cp_wait1();
        __syncthreads();
        if (kt + 2 < nt) {
            int k0 = (kt + 2) << 5;
            #pragma unroll
            for (int i = 0; i < 4; i++)
                cp16(sA + ld*aStageB + i*32*HA_STRIDE*2, Ag + k0 + (size_t)(32*i)*K);
            #pragma unroll
            for (int i = 0; i < 4; i++)
                cp16(sB + ld*bStageB + i*8*HB_STRIDE*2, Bg + (size_t)(k0 + 8*i)*N);
        }
        cp_commit();

        const __half* Ast = Asm + st*HA_TILE;
        const __half* Bst = Bsm + st*HB_TILE;
        #pragma unroll
        for (int kk = 0; kk < 32; kk += 16) {
            HFragA af[4];
            HFragB bf[4];
            #pragma unroll
            for (int mi = 0; mi < 4; mi++)
                wmma::load_matrix_sync(af[mi], Ast + (wy*64 + mi*16)*HA_STRIDE + kk, HA_STRIDE);
            #pragma unroll
            for (int ni = 0; ni < 4; ni++)
                wmma::load_matrix_sync(bf[ni], Bst + kk*HB_STRIDE + wx*64 + ni*16, HB_STRIDE);
            #pragma unroll
            for (int mi = 0; mi < 4; mi++)
                #pragma unroll
                for (int ni = 0; ni < 4; ni++)
                    wmma::mma_sync(acc[mi][ni], af[mi], bf[ni], acc[mi][ni]);
        }
        st++; if (st == GSTAGES) st = 0;
        ld++; if (ld == GSTAGES) ld = 0;
    }

    #pragma unroll
    for (int mi = 0; mi < 4; mi++)
        #pragma unroll
        for (int ni = 0; ni < 4; ni++) {
            float* cp = C + (brow + wy*64 + mi*16)*N + bcol + wx*64 + ni*16;
            if (beta) {
                HFragC cf;
                wmma::load_matrix_sync(cf, cp, N, wmma::mem_row_major);
                #pragma unroll
                for (int t = 0; t < cf.num_elements; t++)
                    acc[mi][ni].x[t] += cf.x[t];
            }
            wmma::store_matrix_sync(cp, acc[mi][ni], N, wmma::mem_row_major);
        }
}

__global__ __launch_bounds__(128, 2)
void sgemm_kernel(const __half* A, const __half* B, float* C, int N, int K, int beta) {
    gemm_core(A, B, C, N, K, beta, blockIdx.y);
}
__global__ __launch_bounds__(128, 2)
void sgemm_batch_kernel(GemmBatch bat, int N, int K, int beta) {
    int y = blockIdx.y;
    GemmDesc dsc = bat.d[bat.yd[y]];
    gemm_core(dsc.A, dsc.B, dsc.C, N, K, beta, bat.yr[y]);
}

/* ------------------------------------------------------------------ */
/* fp16 WMMA flash attention with fused RoPE.                         */
/* QK^T: fp16 hi/lo split (22-bit); PV plain fp16; softmax fp32.      */
/* ------------------------------------------------------------------ */
#define HSTR 72
#define HT   (64*HSTR)
#define FSTR 68
#define FT   (64*FSTR)
#define ATTN_SMEM (6*HT*2 + 2*FT*4 + 512)

typedef wmma::fragment<wmma::matrix_a, 16,16,16, __half, wmma::row_major> AFragA;
typedef wmma::fragment<wmma::matrix_b, 16,16,16, __half, wmma::col_major> AFragBc;
typedef wmma::fragment<wmma::matrix_b, 16,16,16, __half, wmma::row_major> AFragB;
typedef wmma::fragment<wmma::accumulator, 16,16,16, float> AFragC;

__global__ __launch_bounds__(128)
void attn_kernel(const float* Q, size_t qz,
                 const float* K1, const float* V1, int n1,
                 const float* K2, const float* V2, size_t kz, int n2,
                 __half* O, size_t oz, int coff) {
    extern __shared__ char smc[];
    __half* Qhi = (__half*)smc;
    __half* Qlo = Qhi + HT;
    __half* Khi = Qlo + HT;
    __half* Klo = Khi + HT;
    __half* Vh  = Klo + HT;
    __half* Ph  = Vh  + HT;
    float*  Ss  = (float*)(Ph + HT);
    float*  Os  = Ss + FT;
    float*  mrow = Os + FT;
    float*  lrow = mrow + 64;

    int z = blockIdx.z;
    Q  += (size_t)z*qz;  K2 += (size_t)z*kz;
    V2 += (size_t)z*kz;  O  += (size_t)z*oz;
    int h  = blockIdx.y;
    int q0 = blockIdx.x*64;
    int tid = threadIdx.x;
    int wid = tid >> 5;
    int r2  = tid >> 1;
    int hf  = tid & 1;
    float sgn = hf ? 1.f : -1.f;

    {
        float qv[32], cs[32], sn[32];
        const float4* qp = (const float4*)(Q + (size_t)(q0+r2)*ND + h*64 + hf*32);
        #pragma unroll
        for (int i = 0; i < 8; i++) {
            float4 t = qp[i];
            qv[4*i]=t.x; qv[4*i+1]=t.y; qv[4*i+2]=t.z; qv[4*i+3]=t.w;
        }
        int pos = coff + q0 + r2;
        const float4* c4 = (const float4*)(g_cs + pos*32);
        const float4* s4 = (const float4*)(g_sn + pos*32);
        #pragma unroll
        for (int i = 0; i < 8; i++) {
            float4 a = c4[i]; cs[4*i]=a.x; cs[4*i+1]=a.y; cs[4*i+2]=a.z; cs[4*i+3]=a.w;
            float4 b = s4[i]; sn[4*i]=b.x; sn[4*i+1]=b.y; sn[4*i+2]=b.z; sn[4*i+3]=b.w;
        }
        __half* qhd = Qhi + r2*HSTR + hf*32;
        __half* qld = Qlo + r2*HSTR + hf*32;
        float* od = Os + r2*FSTR + hf*32;
        #pragma unroll
        for (int c = 0; c < 32; c++) {
            float o = __shfl_xor_sync(0xffffffffu, qv[c], 1);
            float x = qv[c]*cs[c] + sgn*o*sn[c];
            __half hx = __float2half_rn(x);
            qhd[c] = hx;
            qld[c] = __float2half_rn(x - __half2float(hx));
            od[c] = 0.f;
        }
        if (tid < 64) { mrow[tid] = -1e30f; lrow[tid] = 0.f; }
    }
    __syncthreads();

    int ntot = n1 + n2;
    int kmax = ntot;
    int vis  = q0 + 64 + coff;
    if (vis < kmax) kmax = vis;

    for (int t0 = 0; t0 < kmax; t0 += 64) {
        {
            int kk = t0 + r2;
            const float *kp, *vp; int pos;
            if (kk < n1) { kp = K1 + (size_t)kk*ND; vp = V1 + (size_t)kk*ND; pos = kk; }
            else { int r = kk - n1; kp = K2 + (size_t)r*ND; vp = V2 + (size_t)r*ND; pos = coff + r; }
            kp += h*64 + hf*32; vp += h*64 + hf*32;
            float kv[32], cs[32], sn[32];
            __half* vd = Vh + r2*HSTR + hf*32;
            #pragma unroll
            for (int i = 0; i < 8; i++) {
                float4 t = ((const float4*)kp)[i];
                kv[4*i]=t.x; kv[4*i+1]=t.y; kv[4*i+2]=t.z; kv[4*i+3]=t.w;
                float4 vv = ((const float4*)vp)[i];
                vd[4*i]   = __float2half_rn(vv.x);
                vd[4*i+1] = __float2half_rn(vv.y);
                vd[4*i+2] = __float2half_rn(vv.z);
                vd[4*i+3] = __float2half_rn(vv.w);
            }
            const float4* c4 = (const float4*)(g_cs + pos*32);
            const float4* s4 = (const float4*)(g_sn + pos*32);
            #pragma unroll
            for (int i = 0; i < 8; i++) {
                float4 a = c4[i]; cs[4*i]=a.x; cs[4*i+1]=a.y; cs[4*i+2]=a.z; cs[4*i+3]=a.w;
                float4 b = s4[i]; sn[4*i]=b.x; sn[4*i+1]=b.y; sn[4*i+2]=b.z; sn[4*i+3]=b.w;
            }
            __half* khd = Khi + r2*HSTR + hf*32;
            __half* kld = Klo + r2*HSTR + hf*32;
            #pragma unroll
            for (int c = 0; c < 32; c++) {
                float o = __shfl_xor_sync(0xffffffffu, kv[c], 1);
                float x = kv[c]*cs[c] + sgn*o*sn[c];
                __half hx = __float2half_rn(x);
                khd[c] = hx;
                kld[c] = __float2half_rn(x - __half2float(hx));
            }
        }
        __syncthreads();

        {
            AFragC sacc[4];
            #pragma unroll
            for (int ni = 0; ni < 4; ni++) wmma::fill_fragment(sacc[ni], 0.f);
            #pragma unroll
            for (int ks = 0; ks < 4; ks++) {
                AFragA ah, al;
                wmma::load_matrix_sync(ah, Qhi + (wid*16)*HSTR + ks*16, HSTR);
                wmma::load_matrix_sync(al, Qlo + (wid*16)*HSTR + ks*16, HSTR);
                #pragma unroll
                for (int ni = 0; ni < 4; ni++) {
                    AFragBc bh, bl;
                    wmma::load_matrix_sync(bh, Khi + (ni*16)*HSTR + ks*16, HSTR);
                    wmma::load_matrix_sync(bl, Klo + (ni*16)*HSTR + ks*16, HSTR);
                    wmma::mma_sync(sacc[ni], ah, bh, sacc[ni]);
                    wmma::mma_sync(sacc[ni], ah, bl, sacc[ni]);
                    wmma::mma_sync(sacc[ni], al, bh, sacc[ni]);
                }
            }
            #pragma unroll
            for (int ni = 0; ni < 4; ni++)
                wmma::store_matrix_sync(Ss + (wid*16)*FSTR + ni*16, sacc[ni],
                                        FSTR, wmma::mem_row_major);
        }
        __syncthreads();

        {
            int moff = q0 + coff - t0;
            int jmax = r2 + moff; if (jmax > 63) jmax = 63;
            float mold = mrow[r2];
            float* srow = Ss + r2*FSTR + hf*32;
            __half* prow = Ph + r2*HSTR + hf*32;
            float sv[32];
            float tmax = -1e30f;
            #pragma unroll
            for (int c = 0; c < 32; c++) {
                int cc = hf*32 + c;
                float s = srow[c]*0.125f;
                sv[c] = s;
                if (cc <= jmax) tmax = fmaxf(tmax, s);
            }
            tmax = fmaxf(tmax, __shfl_xor_sync(0xffffffffu, tmax, 1));
            float mnew = fmaxf(mold, tmax);
            float corr = expf(mold - mnew);
            float psum = 0.f;
            #pragma unroll
            for (int c = 0; c < 32; c++) {
                int cc = hf*32 + c;
                float p = (cc <= jmax) ? expf(sv[c] - mnew) : 0.f;
                prow[c] = __float2half_rn(p);
                psum += p;
            }
            psum += __shfl_xor_sync(0xffffffffu, psum, 1);
            if (hf == 0) { mrow[r2] = mnew; lrow[r2] = lrow[r2]*corr + psum; }
            float* orow = Os + r2*FSTR + hf*32;
            #pragma unroll
            for (int c = 0; c < 32; c++) orow[c] *= corr;
        }
        __syncthreads();

        {
            AFragC oacc[4];
            #pragma unroll
            for (int ni = 0; ni < 4; ni++)
                wmma::load_matrix_sync(oacc[ni], Os + (wid*16)*FSTR + ni*16,
                                       FSTR, wmma::mem_row_major);
            #pragma unroll
            for (int ks = 0; ks < 4; ks++) {
                AFragA pf;
                wmma::load_matrix_sync(pf, Ph + (wid*16)*HSTR + ks*16, HSTR);
                #pragma unroll
                for (int ni = 0; ni < 4; ni++) {
                    AFragB vf;
                    wmma::load_matrix_sync(vf, Vh + (ks*16)*HSTR + ni*16, HSTR);
                    wmma::mma_sync(oacc[ni], pf, vf, oacc[ni]);
                }
            }
            #pragma unroll
            for (int ni = 0; ni < 4; ni++)
                wmma::store_matrix_sync(Os + (wid*16)*FSTR + ni*16, oacc[ni],
                                        FSTR, wmma::mem_row_major);
        }
        __syncthreads();
    }

    {
        float invl = 1.f/lrow[r2];
        const float* orow = Os + r2*FSTR + hf*32;
        __half* op = O + (size_t)(q0+r2)*ND + h*64 + hf*32;
        #pragma unroll
        for (int c = 0; c < 32; c++) op[c] = __float2half_rn(orow[c]*invl);
    }
}

/* ------------------------------------------------------------------ */
__global__ void silumul_kernel(const float* __restrict__ a, const float* __restrict__ b,
                               __half* __restrict__ o, int n) {
    int i = blockIdx.x*blockDim.x + threadIdx.x;
    if (i >= n) return;
    float g = a[i];
    o[i] = __float2half_rn((g / (1.f + expf(-g))) * b[i]);
}

__global__ void gate_out_kernel(const float* __restrict__ mem,
                                const float* __restrict__ inj,
                                const float* __restrict__ fg,
                                float* __restrict__ out, int n) {
    int i = blockIdx.x*blockDim.x + threadIdx.x;
    if (i >= n) return;
    float g = 1.f / (1.f + expf(-fg[i]));
    out[i] = mem[i]*g + inj[i]*(1.f - g);
}

/* ================================================================== */
extern "C" void kernel_launch(void* const* d_in, const int* in_sizes, int n_in,
                              void* d_out, int out_size) {
    const int*   ids    = (const int*)d_in[0];
    const float* memory = (const float*)d_in[1];
    const float* beacon = (const float*)d_in[2];
    const float* forget = (const float*)d_in[3];
    const float* embed  = (const float*)d_in[4];
    const float* ln1    = (const float*)d_in[5];
    const float* ln2    = (const float*)d_in[6];
    const float* Wq  = (const float*)d_in[7];
    const float* Wk  = (const float*)d_in[8];
    const float* Wv  = (const float*)d_in[9];
    const float* Wo  = (const float*)d_in[10];
    const float* mWk = (const float*)d_in[11];
    const float* mWv = (const float*)d_in[12];
    const float* bWq = (const float*)d_in[13];
    const float* bWk = (const float*)d_in[14];
    const float* bWv = (const float*)d_in[15];
    const float* fWq = (const float*)d_in[16];
    const float* fWk = (const float*)d_in[17];
    const float* fWv = (const float*)d_in[18];
    const float* Wg  = (const float*)d_in[19];
    const float* Wu  = (const float*)d_in[20];
    const float* Wd  = (const float*)d_in[21];

    static int attr_set = 0;
    static cudaStream_t s2;
    static cudaEvent_t eA, eG;
    if (!attr_set) {
        cudaFuncSetAttribute(sgemm_kernel, cudaFuncAttributeMaxDynamicSharedMemorySize, GSMEM_BYTES);
        cudaFuncSetAttribute(sgemm_batch_kernel, cudaFuncAttributeMaxDynamicSharedMemorySize, GSMEM_BYTES);
        cudaFuncSetAttribute(attn_kernel, cudaFuncAttributeMaxDynamicSharedMemorySize, ATTN_SMEM);
        cudaStreamCreateWithFlags(&s2, cudaStreamNonBlocking);
        cudaEventCreateWithFlags(&eA, cudaEventDisableTiming);
        cudaEventCreateWithFlags(&eG, cudaEventDisableTiming);
        attr_set = 1;
    }

    float *cat,*q,*k,*v,*qbf,*kbf,*vbf,*m1,*m2,*inj,*fg;
    __half *xh,*atth,*m1h,*memh;
    __half *wq,*wk,*wv,*wo,*mwk,*mwv,*bwq,*bwk,*bwv,*fwq,*fwk,*fwv,*wg,*wu,*wd;
    cudaGetSymbolAddress((void**)&cat, g_cat);
    cudaGetSymbolAddress((void**)&xh,  g_xh);
    cudaGetSymbolAddress((void**)&q,   g_q);
    cudaGetSymbolAddress((void**)&k,   g_k);
    cudaGetSymbolAddress((void**)&v,   g_v);
    cudaGetSymbolAddress((void**)&qbf, g_qbf);
    cudaGetSymbolAddress((void**)&kbf, g_kbf);
    cudaGetSymbolAddress((void**)&vbf, g_vbf);
    cudaGetSymbolAddress((void**)&atth,g_atth);
    cudaGetSymbolAddress((void**)&m1,  g_m1);
    cudaGetSymbolAddress((void**)&m2,  g_m2);
    cudaGetSymbolAddress((void**)&m1h, g_m1h);
    cudaGetSymbolAddress((void**)&inj, g_inj);
    cudaGetSymbolAddress((void**)&fg,  g_fg);
    cudaGetSymbolAddress((void**)&memh,g_memh);
    cudaGetSymbolAddress((void**)&wq,  g_wq);
    cudaGetSymbolAddress((void**)&wk,  g_wk);
    cudaGetSymbolAddress((void**)&wv,  g_wv);
    cudaGetSymbolAddress((void**)&wo,  g_wo);
    cudaGetSymbolAddress((void**)&mwk, g_mwk);
    cudaGetSymbolAddress((void**)&mwv, g_mwv);
    cudaGetSymbolAddress((void**)&bwq, g_bwq);
    cudaGetSymbolAddress((void**)&bwk, g_bwk);
    cudaGetSymbolAddress((void**)&bwv, g_bwv);
    cudaGetSymbolAddress((void**)&fwq, g_fwq);
    cudaGetSymbolAddress((void**)&fwk, g_fwk);
    cudaGetSymbolAddress((void**)&fwv, g_fwv);
    cudaGetSymbolAddress((void**)&wg,  g_wg);
    cudaGetSymbolAddress((void**)&wu,  g_wu);
    cudaGetSymbolAddress((void**)&wd,  g_wd);

    const size_t RECB = (size_t)NM*ND*sizeof(float);
    const size_t wdd = (size_t)ND*ND;
    const int DD4 = ND*ND/4, DF4 = ND*NF/4, MEM4 = NM*ND/4;

    auto round_layer = [&](int l, cudaStream_t st) {
        RoundJobs js;
        js.j[0]  = { Wq  + l*wdd, wq  + l*wdd, DD4 };
        js.j[1]  = { Wk  + l*wdd, wk  + l*wdd, DD4 };
        js.j[2]  = { Wv  + l*wdd, wv  + l*wdd, DD4 };
        js.j[3]  = { Wo  + l*wdd, wo  + l*wdd, DD4 };
        js.j[4]  = { mWk + l*wdd, mwk + l*wdd, DD4 };
        js.j[5]  = { mWv + l*wdd, mwv + l*wdd, DD4 };
        js.j[6]  = { bWq + l*wdd, bwq + l*wdd, DD4 };
        js.j[7]  = { bWk + l*wdd, bwk + l*wdd, DD4 };
        js.j[8]  = { bWv + l*wdd, bwv + l*wdd, DD4 };
        js.j[9]  = { fWq + l*wdd, fwq + l*wdd, DD4 };
        js.j[10] = { fWk + l*wdd, fwk + l*wdd, DD4 };
        js.j[11] = { fWv + l*wdd, fwv + l*wdd, DD4 };
        js.j[12] = { Wg + (size_t)l*ND*NF, wg + (size_t)l*ND*NF, DF4 };
        js.j[13] = { Wu + (size_t)l*ND*NF, wu + (size_t)l*ND*NF, DF4 };
        js.j[14] = { Wd + (size_t)l*NF*ND, wd + (size_t)l*NF*ND, DF4 };
        js.j[15] = { memory + (size_t)l*NM*ND, memh + (size_t)l*NM*ND, MEM4 };
        round_w_kernel<<<dim3(256, 16), 256, 0, st>>>(js);
    };

    init_tables_kernel<<<(NPOS*32+255)/256, 256>>>();
    gather_kernel<<<NS, 256>>>(ids, embed, cat);
    round_layer(0, 0);
    cudaMemcpyAsync(cat + (size_t)NS*ND,      beacon, RECB, cudaMemcpyDeviceToDevice, 0);
    cudaMemcpyAsync(cat + (size_t)(NS+NM)*ND, forget, RECB, cudaMemcpyDeviceToDevice, 0);

    /* layer-0 ln1: hidden rows + gate rows (with layer-0 record) */
    rmsnorm_kernel<<<NS, 256>>>(cat, ln1, xh, (float*)0, (float*)0);
    rmsnorm_kernel<<<2*NM, 256>>>(cat + (size_t)NS*ND, ln1, xh + (size_t)NS*ND,
                                  inj, fg);

    for (int l = 0; l < 7; l++) {
        const __half* Wq_l  = wq  + l*wdd;  const __half* Wk_l  = wk  + l*wdd;
        const __half* Wv_l  = wv  + l*wdd;  const __half* Wo_l  = wo  + l*wdd;
        const __half* mWk_l = mwk + l*wdd;  const __half* mWv_l = mwv + l*wdd;
        const __half* bWq_l = bwq + l*wdd;  const __half* bWk_l = bwk + l*wdd;
        const __half* bWv_l = bwv + l*wdd;  const __half* fWq_l = fwq + l*wdd;
        const __half* fWk_l = fwk + l*wdd;  const __half* fWv_l = fwv + l*wdd;
        const __half* Wg_l  = wg + (size_t)l*ND*NF;
        const __half* Wu_l  = wu + (size_t)l*ND*NF;
        const __half* Wd_l  = wd + (size_t)l*NF*ND;
        const __half* mem_l = memh + (size_t)l*NM*ND;
        const bool last = (l == 6);

        /* wait for prior layer's gate chain (gate-x + rounded weights) */
        if (l > 0) cudaStreamWaitEvent(0, eG, 0);

        /* ALL projections in one packed batched launch (main) */
        {
            GemmBatch ba; int nb = 0, ny = 0;
            const __half* bx = xh + (size_t)NS*ND;
            const __half* fx = xh + (size_t)(NS+NM)*ND;
            int nrbs[12];
            if (!last) { ba.d[nb] = { xh, Wq_l, q }; nrbs[nb++] = 8; }
            ba.d[nb] = { xh, Wk_l, k + (size_t)NM*ND }; nrbs[nb++] = 8;
            ba.d[nb] = { xh, Wv_l, v + (size_t)NM*ND }; nrbs[nb++] = 8;
            ba.d[nb] = { mem_l, mWk_l, k };   nrbs[nb++] = 1;
            ba.d[nb] = { mem_l, mWv_l, v };   nrbs[nb++] = 1;
            ba.d[nb] = { bx, bWq_l, qbf };    nrbs[nb++] = 1;
            ba.d[nb] = { bx, bWk_l, kbf };    nrbs[nb++] = 1;
            ba.d[nb] = { bx, bWv_l, vbf };    nrbs[nb++] = 1;
            ba.d[nb] = { fx, fWq_l, qbf + (size_t)NM*ND }; nrbs[nb++] = 1;
            ba.d[nb] = { fx, fWk_l, kbf + (size_t)NM*ND }; nrbs[nb++] = 1;
            ba.d[nb] = { fx, fWv_l, vbf + (size_t)NM*ND }; nrbs[nb++] = 1;
            for (int di = 0; di < nb; di++)
                for (int rb = 0; rb < nrbs[di]; rb++) {
                    ba.yd[ny] = (unsigned char)di;
                    ba.yr[ny] = (unsigned char)rb; ny++;
                }
            sgemm_batch_kernel<<<dim3(8, ny, 1), 128, GSMEM_BYTES>>>(ba, ND, ND, 0);
        }

        if (!last) {
            cudaEventRecord(eA, 0);
            cudaStreamWaitEvent(s2, eA, 0);

            /* ---- gate chain on s2 ---- */
            attn_kernel<<<dim3(NM/64, NH, 2), 128, ATTN_SMEM, s2>>>(
                    qbf, (size_t)NM*ND, k, v, NKV,
                    kbf, vbf, (size_t)NM*ND, NM,
                    atth + (size_t)NS*ND, (size_t)NM*ND, NKV);
            sgemm_kernel<<<dim3(8, 2), 128, GSMEM_BYTES, s2>>>(
                    atth + (size_t)NS*ND, Wo_l, cat + (size_t)NS*ND, ND, ND, 1);
            rmsnorm_kernel<<<2*NM, 256, 0, s2>>>(cat + (size_t)NS*ND,
                    ln2 + (size_t)l*ND, xh + (size_t)NS*ND, (float*)0, (float*)0);
            {
                GemmBatch gb; int ny = 0;
                gb.d[0] = { xh + (size_t)NS*ND, Wg_l, m1 + (size_t)NS*NF };
                gb.d[1] = { xh + (size_t)NS*ND, Wu_l, m2 + (size_t)NS*NF };
                for (int di = 0; di < 2; di++)
                    for (int rb = 0; rb < 2; rb++) {
                        gb.yd[ny] = (unsigned char)di;
                        gb.yr[ny] = (unsigned char)rb; ny++;
                    }
                sgemm_batch_kernel<<<dim3(NF/128, ny, 1), 128, GSMEM_BYTES, s2>>>(gb, NF, ND, 0);
            }
            silumul_kernel<<<(2*NM*NF)/256, 256, 0, s2>>>(
                    m1 + (size_t)NS*NF, m2 + (size_t)NS*NF, m1h + (size_t)NS*NF, 2*NM*NF);
            sgemm_kernel<<<dim3(8, 2), 128, GSMEM_BYTES, s2>>>(
                    m1h + (size_t)NS*NF, Wd_l, cat + (size_t)NS*ND, ND, NF, 1);
            round_layer(l + 1, s2);
            /* gate ln1 for layer l+1 (+ record of layer-(l+1) entry) */
            rmsnorm_kernel<<<2*NM, 256, 0, s2>>>(cat + (size_t)NS*ND,
                    ln1 + (size_t)(l+1)*ND, xh + (size_t)NS*ND,
                    inj + (size_t)(l+1)*NM*ND, fg + (size_t)(l+1)*NM*ND);
            cudaEventRecord(eG, s2);

            /* ---- hidden chain on main ---- */
            attn_kernel<<<dim3(NS/64, NH, 1), 128, ATTN_SMEM>>>(q, 0, k, v, NKV,
                    k, v, 0, 0, atth, 0, NM);
            sgemm_kernel<<<dim3(8, 8), 128, GSMEM_BYTES>>>(atth, Wo_l, cat, ND, ND, 1);
            rmsnorm_kernel<<<NS, 256>>>(cat, ln2 + (size_t)l*ND, xh, (float*)0, (float*)0);
            {
                GemmBatch gh; int ny = 0;
                gh.d[0] = { xh, Wg_l, m1 };
                gh.d[1] = { xh, Wu_l, m2 };
                for (int di = 0; di < 2; di++)
                    for (int rb = 0; rb < 8; rb++) {
                        gh.yd[ny] = (unsigned char)di;
                        gh.yr[ny] = (unsigned char)rb; ny++;
                    }
                sgemm_batch_kernel<<<dim3(NF/128, ny, 1), 128, GSMEM_BYTES>>>(gh, NF, ND, 0);
            }
            silumul_kernel<<<(NS*NF)/256, 256>>>(m1, m2, m1h, NS*NF);
            sgemm_kernel<<<dim3(8, 8), 128, GSMEM_BYTES>>>(m1h, Wd_l, cat, ND, NF, 1);
            /* hidden ln1 for layer l+1 */
            rmsnorm_kernel<<<NS, 256>>>(cat, ln1 + (size_t)(l+1)*ND, xh,
                                        (float*)0, (float*)0);
        } else {
            /* last layer: only the gate rows matter; run on main */
            attn_kernel<<<dim3(NM/64, NH, 2), 128, ATTN_SMEM>>>(
                    qbf, (size_t)NM*ND, k, v, NKV,
                    kbf, vbf, (size_t)NM*ND, NM,
                    atth + (size_t)NS*ND, (size_t)NM*ND, NKV);
            sgemm_kernel<<<dim3(8, 2), 128, GSMEM_BYTES>>>(
                    atth + (size_t)NS*ND, Wo_l, cat + (size_t)NS*ND, ND, ND, 1);
            rmsnorm_kernel<<<2*NM, 256>>>(cat + (size_t)NS*ND,
                    ln2 + (size_t)l*ND, xh + (size_t)NS*ND, (float*)0, (float*)0);
            {
                GemmBatch gb; int ny = 0;
                gb.d[0] = { xh + (size_t)NS*ND, Wg_l, m1 + (size_t)NS*NF };
                gb.d[1] = { xh + (size_t)NS*ND, Wu_l, m2 + (size_t)NS*NF };
                for (int di = 0; di < 2; di++)
                    for (int rb = 0; rb < 2; rb++) {
                        gb.yd[ny] = (unsigned char)di;
                        gb.yr[ny] = (unsigned char)rb; ny++;
                    }
                sgemm_batch_kernel<<<dim3(NF/128, ny, 1), 128, GSMEM_BYTES>>>(gb, NF, ND, 0);
            }
            silumul_kernel<<<(2*NM*NF)/256, 256>>>(
                    m1 + (size_t)NS*NF, m2 + (size_t)NS*NF, m1h + (size_t)NS*NF, 2*NM*NF);
            sgemm_kernel<<<dim3(8, 2), 128, GSMEM_BYTES>>>(
                    m1h + (size_t)NS*NF, Wd_l, cat + (size_t)NS*ND, ND, NF, 1);
        }
    }

    /* layer-7 entry record = layer-6 output (gate rows) */
    cudaMemcpyAsync(inj + (size_t)7*NM*ND, cat + (size_t)NS*ND,      RECB, cudaMemcpyDeviceToDevice, 0);
    cudaMemcpyAsync(fg  + (size_t)7*NM*ND, cat + (size_t)(NS+NM)*ND, RECB, cudaMemcpyDeviceToDevice, 0);

    gate_out_kernel<<<(NL*NM*ND)/256, 256>>>(memory, inj, fg, (float*)d_out, NL*NM*ND);
}